// round 7
// baseline (speedup 1.0000x reference)
#include <cuda_runtime.h>
#include <stdint.h>

#define N_NODES 100000
#define DIM     256
#define NS      64
#define NPC     256                 // nodes per CTA in k_gemm
#define NSLICE  8                   // slices per sample in k_cand
#define SLICEN  (N_NODES / NSLICE)  // 12500
#define CANDN   160
#define TK      8
#define MODCAP  128
#define BMW     (N_NODES / 32)      // 3125
#define HSHN    2048

typedef unsigned long long u64;

// -------- scratch (static device globals; no runtime allocation) --------
__device__ float g_D[(size_t)NS * N_NODES];            // D[s][j] = dot(x_s, V_j)
__device__ float g_DT[(size_t)N_NODES * NS];           // DT[j][s] (transposed, immutable baseline)
__device__ float g_vn[N_NODES];                        // ||V_j||^2
__device__ float g_G[NS * NS];                         // Gram of X (diag = ||x||^2)
__device__ u64   g_scand[(size_t)NS * NSLICE * CANDN]; // per (sample,slice) sorted keys
__device__ u64   g_cand[NS * CANDN];                   // per sample global top-160

__device__ __forceinline__ u64 u64min(u64 a, u64 b) { return a < b ? a : b; }
__device__ __forceinline__ u64 u64max(u64 a, u64 b) { return a > b ? a : b; }

__device__ __forceinline__ u64 f2fma(u64 a, u64 b, u64 c) {
    u64 d;
    asm("fma.rn.f32x2 %0, %1, %2, %3;" : "=l"(d) : "l"(a), "l"(b), "l"(c));
    return d;
}
__device__ __forceinline__ u64 fpack(float x) {
    u64 d;
    asm("mov.b64 %0, {%1, %1};" : "=l"(d) : "r"(__float_as_uint(x)));
    return d;
}
__device__ __forceinline__ void funpack(u64 v, float& lo, float& hi) {
    unsigned a, b;
    asm("mov.b64 {%0, %1}, %2;" : "=r"(a), "=r"(b) : "l"(v));
    lo = __uint_as_float(a); hi = __uint_as_float(b);
}

// ---------------- K0: profiling-slot shims (no work) ----------------
__global__ void k_nop() {}

// ---------------- K1: Gram matrix G = X X^T ----------------
__global__ void k_gram(const float* __restrict__ X) {
    __shared__ float sx[DIM];
    __shared__ float red[256];
    int b = blockIdx.x, tid = threadIdx.x;
    sx[tid] = X[b * DIM + tid];
    __syncthreads();
    int j = tid & 63, q = tid >> 6;
    const float* xj = X + (size_t)j * DIM + q * 64;
    const float* xb = sx + q * 64;
    float p = 0.f;
#pragma unroll
    for (int k = 0; k < 64; ++k) p += xb[k] * xj[k];
    red[tid] = p;
    __syncthreads();
    if (tid < 64)
        g_G[b * NS + tid] = red[tid] + red[tid + 64] + red[tid + 128] + red[tid + 192];
}

// ---------------- K2: D = X V^T (+ DT) and vnorms; 8x8 FFMA2 tile, reg double-buffer ----------------
__global__ __launch_bounds__(256) void k_gemm(const float* __restrict__ X, const float* __restrict__ V) {
    __shared__ __align__(16) float sX[32][68];    // [k][s]
    __shared__ __align__(16) float sV[32][260];   // [k][j]
    int tid = threadIdx.x;
    int j0 = blockIdx.x * NPC;
    int nvalid = N_NODES - j0; if (nvalid > NPC) nvalid = NPC;

    int sg = tid & 7, ng = tid >> 3;      // compute mapping: 8 sample-groups x 32 node-groups
    int xs = tid & 63, xf = tid >> 6;     // X loader
    bool vok = tid < nvalid;
    const float* Vrow = V + (size_t)(vok ? (j0 + tid) : 0) * DIM;
    const float* Xrow = X + (size_t)xs * DIM;

    u64 acc[8][4];
#pragma unroll
    for (int a = 0; a < 8; ++a)
#pragma unroll
        for (int p = 0; p < 4; ++p) acc[a][p] = 0ull;
    float vnacc = 0.f;

    float4 rfx[2], rfv[8];
#pragma unroll
    for (int u = 0; u < 2; ++u) rfx[u] = *(const float4*)(Xrow + xf * 8 + u * 4);
#pragma unroll
    for (int u = 0; u < 8; ++u)
        rfv[u] = vok ? *(const float4*)(Vrow + u * 4) : make_float4(0.f, 0.f, 0.f, 0.f);

    for (int kc = 0; kc < DIM; kc += 32) {
#pragma unroll
        for (int u = 0; u < 2; ++u) {
            int kof = xf * 8 + u * 4;
            sX[kof + 0][xs] = rfx[u].x; sX[kof + 1][xs] = rfx[u].y;
            sX[kof + 2][xs] = rfx[u].z; sX[kof + 3][xs] = rfx[u].w;
        }
#pragma unroll
        for (int u = 0; u < 8; ++u) {
            int kof = u * 4;
            sV[kof + 0][tid] = rfv[u].x; sV[kof + 1][tid] = rfv[u].y;
            sV[kof + 2][tid] = rfv[u].z; sV[kof + 3][tid] = rfv[u].w;
            vnacc += rfv[u].x * rfv[u].x + rfv[u].y * rfv[u].y
                   + rfv[u].z * rfv[u].z + rfv[u].w * rfv[u].w;
        }
        __syncthreads();
        if (kc + 32 < DIM) {   // prefetch next chunk into registers (overlaps compute)
#pragma unroll
            for (int u = 0; u < 2; ++u)
                rfx[u] = *(const float4*)(Xrow + kc + 32 + xf * 8 + u * 4);
#pragma unroll
            for (int u = 0; u < 8; ++u)
                rfv[u] = vok ? *(const float4*)(Vrow + kc + 32 + u * 4)
                             : make_float4(0.f, 0.f, 0.f, 0.f);
        }
#pragma unroll
        for (int kk = 0; kk < 32; ++kk) {
            float4 xa = *(const float4*)&sX[kk][sg * 8];
            float4 xb = *(const float4*)&sX[kk][sg * 8 + 4];
            ulonglong2 va = *(const ulonglong2*)&sV[kk][ng * 8];
            ulonglong2 vb = *(const ulonglong2*)&sV[kk][ng * 8 + 4];
            u64 xp[8];
            xp[0] = fpack(xa.x); xp[1] = fpack(xa.y); xp[2] = fpack(xa.z); xp[3] = fpack(xa.w);
            xp[4] = fpack(xb.x); xp[5] = fpack(xb.y); xp[6] = fpack(xb.z); xp[7] = fpack(xb.w);
#pragma unroll
            for (int a = 0; a < 8; ++a) {
                acc[a][0] = f2fma(xp[a], va.x, acc[a][0]);
                acc[a][1] = f2fma(xp[a], va.y, acc[a][1]);
                acc[a][2] = f2fma(xp[a], vb.x, acc[a][2]);
                acc[a][3] = f2fma(xp[a], vb.y, acc[a][3]);
            }
        }
        __syncthreads();
    }

    if (vok) g_vn[j0 + tid] = vnacc;

    float accf[8][8];
#pragma unroll
    for (int a = 0; a < 8; ++a)
#pragma unroll
        for (int p = 0; p < 4; ++p) funpack(acc[a][p], accf[a][2 * p], accf[a][2 * p + 1]);

    int jb = ng * 8;
    if (jb < nvalid) {
        bool full = (jb + 8 <= nvalid);
#pragma unroll
        for (int a = 0; a < 8; ++a) {
            int s = sg * 8 + a;
            float* dst = g_D + (size_t)s * N_NODES + j0 + jb;
            if (full) {
                *(float4*)dst       = make_float4(accf[a][0], accf[a][1], accf[a][2], accf[a][3]);
                *(float4*)(dst + 4) = make_float4(accf[a][4], accf[a][5], accf[a][6], accf[a][7]);
            } else {
                for (int c = 0; c < 8; ++c) if (jb + c < nvalid) dst[c] = accf[a][c];
            }
        }
#pragma unroll
        for (int c = 0; c < 8; ++c) {
            if (full || jb + c < nvalid) {
                float* dst = &g_DT[(size_t)(j0 + jb + c) * NS + sg * 8];
                *(float4*)dst       = make_float4(accf[0][c], accf[1][c], accf[2][c], accf[3][c]);
                *(float4*)(dst + 4) = make_float4(accf[4][c], accf[5][c], accf[6][c], accf[7][c]);
            }
        }
    }
}

// ---------------- K3: per (sample,slice) top-CANDN via PQ + top-k selection network ----------------
__global__ __launch_bounds__(256) void k_cand() {
    __shared__ u64 keys[2048];
    int slice = blockIdx.x, i = blockIdx.y, tid = threadIdx.x;
    float xn = __ldg(&g_G[i * NS + i]);
    const float* Drow = g_D + (size_t)i * N_NODES;
    int base = slice * SLICEN, jend = base + SLICEN;

    u64 K[TK];
#pragma unroll
    for (int m = 0; m < TK; ++m) K[m] = ~0ull;

    for (int j = base + tid; j < jend; j += 1024) {
        float d[4]; int jj[4]; bool ok[4];
#pragma unroll
        for (int q = 0; q < 4; ++q) {
            jj[q] = j + q * 256;
            ok[q] = jj[q] < jend;
            int js = ok[q] ? jj[q] : base;
            d[q] = xn - 2.f * __ldg(&Drow[js]) + __ldg(&g_vn[js]);
        }
#pragma unroll
        for (int q = 0; q < 4; ++q) {
            if (ok[q]) {
                u64 key = ((u64)__float_as_uint(d[q]) << 32) | (unsigned)jj[q];
                if (key < K[TK - 1]) {
                    K[TK - 1] = key;
#pragma unroll
                    for (int m = TK - 1; m > 0; --m) {
                        u64 a = u64min(K[m - 1], K[m]);
                        u64 b = u64max(K[m - 1], K[m]);
                        K[m - 1] = a; K[m] = b;
                    }
                }
            }
        }
    }
    // store per-thread run; odd threads reversed so 16-blocks are bitonic
#pragma unroll
    for (int m = 0; m < TK; ++m)
        keys[tid * TK + m] = (tid & 1) ? K[TK - 1 - m] : K[m];
    __syncthreads();

    // bitonic continue from k=16 up to 256 (final level forced ascending per 256-block)
    for (int k = 16; k <= 256; k <<= 1) {
        for (int j2 = k >> 1; j2 > 0; j2 >>= 1) {
            for (int t = tid; t < 1024; t += 256) {
                int a = ((t & ~(j2 - 1)) << 1) | (t & (j2 - 1));
                bool up = (k == 256) ? true : ((a & k) == 0);
                u64 x = keys[a], y = keys[a + j2];
                if ((x > y) == up) { keys[a] = y; keys[a + j2] = x; }
            }
            __syncthreads();
        }
    }
    // top-k merge: 8 sorted 256-blocks -> 256 via halver + clean, 3 levels
#pragma unroll
    for (int L = 0; L < 3; ++L) {
        int npairs = 4 >> L;
        int pairstride = 512 << L;
        int nops = npairs << 8;
        for (int t = tid; t < nops; t += 256) {
            int p = t >> 8, ii = t & 255;
            int a = p * pairstride + ii;
            int b = p * pairstride + (pairstride >> 1) + 255 - ii;
            u64 x = keys[a], y = keys[b];
            if (y < x) { keys[a] = y; keys[b] = x; }
        }
        __syncthreads();
        for (int j2 = 128; j2 > 0; j2 >>= 1) {
            int cops = npairs << 7;
            for (int t = tid; t < cops; t += 256) {
                int p = t >> 7, q = t & 127;
                int idx = ((q & ~(j2 - 1)) << 1) | (q & (j2 - 1));
                int a = p * pairstride + idx;
                u64 x = keys[a], y = keys[a + j2];
                if (y < x) { keys[a] = y; keys[a + j2] = x; }
            }
            __syncthreads();
        }
    }
    if (tid < CANDN)
        g_scand[((size_t)i * NSLICE + slice) * CANDN + tid] = keys[tid];
}

// ---------------- K3b: merge 8 sorted lists -> global top-160 ----------------
__global__ __launch_bounds__(512) void k_merge() {
    __shared__ u64 keys[2048];
    int i = blockIdx.x, tid = threadIdx.x;
    for (int t = tid; t < 2048; t += 512) {
        int list = t >> 8, pos = t & 255;
        keys[t] = (pos < CANDN) ? __ldg(&g_scand[((size_t)i * NSLICE + list) * CANDN + pos]) : ~0ull;
    }
    __syncthreads();
#pragma unroll
    for (int L = 0; L < 3; ++L) {
        int npairs = 4 >> L;
        int pairstride = 512 << L;
        int nops = npairs << 8;
        for (int t = tid; t < nops; t += 512) {
            int p = t >> 8, ii = t & 255;
            int a = p * pairstride + ii;
            int b = p * pairstride + (pairstride >> 1) + 255 - ii;
            u64 x = keys[a], y = keys[b];
            if (y < x) { keys[a] = y; keys[b] = x; }
        }
        __syncthreads();
        for (int j2 = 128; j2 > 0; j2 >>= 1) {
            int cops = npairs << 7;
            for (int t = tid; t < cops; t += 512) {
                int p = t >> 7, q = t & 127;
                int idx = ((q & ~(j2 - 1)) << 1) | (q & (j2 - 1));
                int a = p * pairstride + idx;
                u64 x = keys[a], y = keys[a + j2];
                if (y < x) { keys[a] = y; keys[a + j2] = x; }
            }
            __syncthreads();
        }
    }
    if (tid < CANDN) g_cand[i * CANDN + tid] = keys[tid];
}

// ---------------- K4: sequential BMU loop, single warp, flat masked selection ----------------
#define SEQ_SMEM (NS * CANDN * 8 + NS * NS * 4 + 64 * 129 * 4 + MODCAP * 4 + MODCAP * 4 + HSHN * 4 + BMW * 4 + 64)

__global__ __launch_bounds__(256) void k_seq(const int* __restrict__ itp, float* __restrict__ out) {
    extern __shared__ char smraw[];
    u64*      scand = (u64*)smraw;                  // NS*CANDN
    float*    sG    = (float*)(scand + NS * CANDN); // NS*NS
    float*    mdt   = sG + NS * NS;                 // 64*129 : mdt[t][m]
    float*    mvn   = mdt + 64 * 129;               // MODCAP
    int*      midx  = (int*)(mvn + MODCAP);         // MODCAP
    int*      hsh   = midx + MODCAP;                // HSHN
    unsigned* bm    = (unsigned*)(hsh + HSHN);      // BMW

    int tid = threadIdx.x;
    for (int t = tid; t < NS * CANDN; t += 256) scand[t] = __ldg(&g_cand[t]);
    for (int t = tid; t < NS * NS; t += 256) sG[t] = __ldg(&g_G[t]);
    for (int t = tid; t < BMW; t += 256) bm[t] = 0;
    for (int t = tid; t < HSHN; t += 256) hsh[t] = 0;
    __syncthreads();
    if (tid >= 32) return;   // single warp

    int lane = tid;
    int it = itp ? __ldg(itp) : 0;
    float eb = 1.0f / (float)(it + 2);
    float en = 1.0f / (float)((it + 1) * 100);
    float ebo = 1.f - eb, eno = 1.f - en;

    // prefetch top-4 candidate DT rows + vnorms for sample 0
    unsigned pi0, pi1, pi2, pi3;
    float pf0a, pf1a, pf2a, pf3a, pf0b, pf1b, pf2b, pf3b, pfvn = 0.f;
    pi0 = (unsigned)scand[0]; pi1 = (unsigned)scand[1];
    pi2 = (unsigned)scand[2]; pi3 = (unsigned)scand[3];
    pf0a = __ldg(&g_DT[(size_t)pi0 * NS + lane]); pf0b = __ldg(&g_DT[(size_t)pi0 * NS + 32 + lane]);
    pf1a = __ldg(&g_DT[(size_t)pi1 * NS + lane]); pf1b = __ldg(&g_DT[(size_t)pi1 * NS + 32 + lane]);
    pf2a = __ldg(&g_DT[(size_t)pi2 * NS + lane]); pf2b = __ldg(&g_DT[(size_t)pi2 * NS + 32 + lane]);
    pf3a = __ldg(&g_DT[(size_t)pi3 * NS + lane]); pf3b = __ldg(&g_DT[(size_t)pi3 * NS + 32 + lane]);
    if (lane < 4) pfvn = __ldg(&g_vn[(unsigned)scand[lane]]);
    int nmod = 0;

    for (int i = 0; i < NS; ++i) {
        float xn = sG[i * NS + i];

        // ---- flat masked selection: unmodified candidates + mod table ----
        u64 k1 = ~0ull, k2 = ~0ull;
#pragma unroll
        for (int q = 0; q < 5; ++q) {
            u64 key = scand[i * CANDN + q * 32 + lane];
            unsigned idx = (unsigned)key;
            if (!((bm[idx >> 5] >> (idx & 31)) & 1u)) {
                if (key < k1) { k2 = k1; k1 = key; } else if (key < k2) k2 = key;
            }
        }
        int qmax = (nmod + 31) >> 5;
        for (int q = 0; q < qmax; ++q) {
            int m = q * 32 + lane;
            if (m < nmod) {
                float d2 = xn - 2.f * mdt[i * 129 + m] + mvn[m];
                u64 key = ((u64)__float_as_uint(d2) << 32) | (unsigned)midx[m];
                if (key < k1) { k2 = k1; k1 = key; } else if (key < k2) k2 = key;
            }
        }
#pragma unroll
        for (int off = 16; off; off >>= 1) {
            u64 b1 = __shfl_xor_sync(0xffffffffu, k1, off);
            u64 b2 = __shfl_xor_sync(0xffffffffu, k2, off);
            u64 m1 = u64min(k1, b1);
            u64 m2 = u64min(u64max(k1, b1), u64min(k2, b2));
            k1 = m1; k2 = m2;
        }
        unsigned nb = (unsigned)k1, nsd = (unsigned)k2;
        bool newb = !((bm[nb >> 5] >> (nb & 31)) & 1u);
        bool news = !((bm[nsd >> 5] >> (nsd & 31)) & 1u);

        if (lane == 2) {
            out[2 * i]     = sqrtf(__uint_as_float((unsigned)(k1 >> 32)) + 1e-12f);
            out[2 * i + 1] = sqrtf(__uint_as_float((unsigned)(k2 >> 32)) + 1e-12f);
        }

        // ---- slot resolution: concurrent probes on lanes 0/1 ----
        int sb = 0, ss = 0;
        if (lane == 0 && !newb) {
            unsigned h = (nb * 2654435761u) >> 21;
            while (true) {
                int e = hsh[h];
                if (e && midx[e - 1] == (int)nb) { sb = e - 1; break; }
                h = (h + 1) & (HSHN - 1);
            }
        }
        if (lane == 1 && !news) {
            unsigned h = (nsd * 2654435761u) >> 21;
            while (true) {
                int e = hsh[h];
                if (e && midx[e - 1] == (int)nsd) { ss = e - 1; break; }
                h = (h + 1) & (HSHN - 1);
            }
        }
        int sbh = __shfl_sync(0xffffffffu, sb, 0);
        int ssh = __shfl_sync(0xffffffffu, ss, 1);
        int slot_b = newb ? nmod : sbh;
        int slot_s = news ? (nmod + (newb ? 1 : 0)) : ssh;

        // ---- gather old rows ----
        float ob0, ob1, os0, os1, vnb, vns;
        if (newb) {
            int sel = (nb == pi0) ? 0 : (nb == pi1) ? 1 : (nb == pi2) ? 2 : (nb == pi3) ? 3 : -1;
            if (sel >= 0) {
                ob0 = sel == 0 ? pf0a : sel == 1 ? pf1a : sel == 2 ? pf2a : pf3a;
                ob1 = sel == 0 ? pf0b : sel == 1 ? pf1b : sel == 2 ? pf2b : pf3b;
                vnb = __shfl_sync(0xffffffffu, pfvn, sel);
            } else {
                ob0 = __ldg(&g_DT[(size_t)nb * NS + lane]);
                ob1 = __ldg(&g_DT[(size_t)nb * NS + 32 + lane]);
                vnb = __ldg(&g_vn[nb]);
            }
        } else {
            ob0 = mdt[lane * 129 + slot_b];
            ob1 = mdt[(32 + lane) * 129 + slot_b];
            vnb = mvn[slot_b];
        }
        if (news) {
            int sel = (nsd == pi0) ? 0 : (nsd == pi1) ? 1 : (nsd == pi2) ? 2 : (nsd == pi3) ? 3 : -1;
            if (sel >= 0) {
                os0 = sel == 0 ? pf0a : sel == 1 ? pf1a : sel == 2 ? pf2a : pf3a;
                os1 = sel == 0 ? pf0b : sel == 1 ? pf1b : sel == 2 ? pf2b : pf3b;
                vns = __shfl_sync(0xffffffffu, pfvn, sel);
            } else {
                os0 = __ldg(&g_DT[(size_t)nsd * NS + lane]);
                os1 = __ldg(&g_DT[(size_t)nsd * NS + 32 + lane]);
                vns = __ldg(&g_vn[nsd]);
            }
        } else {
            os0 = mdt[lane * 129 + slot_s];
            os1 = mdt[(32 + lane) * 129 + slot_s];
            vns = mvn[slot_s];
        }
        float obi = __shfl_sync(0xffffffffu, (i < 32) ? ob0 : ob1, i & 31);
        float osi = __shfl_sync(0xffffffffu, (i < 32) ? os0 : os1, i & 31);

        __syncwarp();   // reads of mdt/mvn/bm/hsh complete before mutation

        float gr0 = sG[i * NS + lane], gr1 = sG[i * NS + 32 + lane];
        mdt[lane * 129 + slot_b]        = ebo * ob0 + eb * gr0;
        mdt[(32 + lane) * 129 + slot_b] = ebo * ob1 + eb * gr1;
        mdt[lane * 129 + slot_s]        = eno * os0 + en * gr0;
        mdt[(32 + lane) * 129 + slot_s] = eno * os1 + en * gr1;
        if (lane == 0) {
            mvn[slot_b] = ebo * ebo * vnb + 2.f * eb * ebo * obi + eb * eb * xn;
            if (newb) {
                midx[slot_b] = (int)nb;
                atomicOr(&bm[nb >> 5], 1u << (nb & 31));
                unsigned h = (nb * 2654435761u) >> 21;
                while (atomicCAS(&hsh[h], 0, slot_b + 1) != 0) h = (h + 1) & (HSHN - 1);
            }
        }
        if (lane == 1) {
            mvn[slot_s] = eno * eno * vns + 2.f * en * eno * osi + en * en * xn;
            if (news) {
                midx[slot_s] = (int)nsd;
                atomicOr(&bm[nsd >> 5], 1u << (nsd & 31));
                unsigned h = (nsd * 2654435761u) >> 21;
                while (atomicCAS(&hsh[h], 0, slot_s + 1) != 0) h = (h + 1) & (HSHN - 1);
            }
        }
        nmod += (newb ? 1 : 0) + (news ? 1 : 0);

        // prefetch next sample's top-4 candidate rows + vnorms (off critical path)
        if (i + 1 < NS) {
            pi0 = (unsigned)scand[(i + 1) * CANDN + 0];
            pi1 = (unsigned)scand[(i + 1) * CANDN + 1];
            pi2 = (unsigned)scand[(i + 1) * CANDN + 2];
            pi3 = (unsigned)scand[(i + 1) * CANDN + 3];
            pf0a = __ldg(&g_DT[(size_t)pi0 * NS + lane]); pf0b = __ldg(&g_DT[(size_t)pi0 * NS + 32 + lane]);
            pf1a = __ldg(&g_DT[(size_t)pi1 * NS + lane]); pf1b = __ldg(&g_DT[(size_t)pi1 * NS + 32 + lane]);
            pf2a = __ldg(&g_DT[(size_t)pi2 * NS + lane]); pf2b = __ldg(&g_DT[(size_t)pi2 * NS + 32 + lane]);
            pf3a = __ldg(&g_DT[(size_t)pi3 * NS + lane]); pf3b = __ldg(&g_DT[(size_t)pi3 * NS + 32 + lane]);
            if (lane < 4) pfvn = __ldg(&g_vn[(unsigned)scand[(i + 1) * CANDN + lane]]);
        }
        __syncwarp();   // mutations visible before next selection
    }
}

extern "C" void kernel_launch(void* const* d_in, const int* in_sizes, int n_in,
                              void* d_out, int out_size) {
    const float* X = (const float*)d_in[0];     // data [64,256]
    const float* V = (const float*)d_in[1];     // V [100000,256]
    const int* itp = (n_in > 3) ? (const int*)d_in[3] : nullptr;
    float* out = (float*)d_out;                 // [64,2]

    cudaFuncSetAttribute(k_seq, cudaFuncAttributeMaxDynamicSharedMemorySize, SEQ_SMEM);

    // two shim launches so ncu's fixed capture slot lands on k_gemm
    k_nop<<<1, 32>>>();
    k_nop<<<1, 32>>>();

    k_gram<<<NS, 256>>>(X);
    k_gemm<<<(N_NODES + NPC - 1) / NPC, 256>>>(X, V);
    k_cand<<<dim3(NSLICE, NS), 256>>>();
    k_merge<<<NS, 512>>>();
    k_seq<<<1, 256, SEQ_SMEM>>>(itp, out);
}

// round 9
// speedup vs baseline: 1.0696x; 1.0696x over previous
#include <cuda_runtime.h>
#include <stdint.h>

#define N_NODES 100000
#define DIM     256
#define NS      64
#define NPC     256                 // nodes per CTA in k_gemm
#define NSLICE  8                   // slices per sample in k_cand
#define SLICEN  (N_NODES / NSLICE)  // 12500
#define CANDN   160
#define TK      8
#define MODCAP  128
#define BMW     (N_NODES / 32)      // 3125
#define HSHN    2048

typedef unsigned long long u64;

// -------- scratch (static device globals; no runtime allocation) --------
__device__ float g_D[(size_t)NS * N_NODES];            // D[s][j] = dot(x_s, V_j)
__device__ float g_DT[(size_t)N_NODES * NS];           // DT[j][s] (transposed, immutable baseline)
__device__ float g_vn[N_NODES];                        // ||V_j||^2
__device__ float g_G[NS * NS];                         // Gram of X (diag = ||x||^2)
__device__ u64   g_scand[(size_t)NS * NSLICE * CANDN]; // per (sample,slice) sorted keys
__device__ u64   g_cand[NS * CANDN];                   // per sample global top-160

__device__ __forceinline__ u64 u64min(u64 a, u64 b) { return a < b ? a : b; }
__device__ __forceinline__ u64 u64max(u64 a, u64 b) { return a > b ? a : b; }

__device__ __forceinline__ u64 f2fma(u64 a, u64 b, u64 c) {
    u64 d;
    asm("fma.rn.f32x2 %0, %1, %2, %3;" : "=l"(d) : "l"(a), "l"(b), "l"(c));
    return d;
}
__device__ __forceinline__ u64 fpack(float x) {
    u64 d;
    asm("mov.b64 %0, {%1, %1};" : "=l"(d) : "r"(__float_as_uint(x)));
    return d;
}
__device__ __forceinline__ void funpack(u64 v, float& lo, float& hi) {
    unsigned a, b;
    asm("mov.b64 {%0, %1}, %2;" : "=r"(a), "=r"(b) : "l"(v));
    lo = __uint_as_float(a); hi = __uint_as_float(b);
}

// ---------------- K0: profiling-slot shim (no work) ----------------
__global__ void k_nop() {}

// ---------------- K1: Gram matrix G = X X^T ----------------
__global__ void k_gram(const float* __restrict__ X) {
    __shared__ float sx[DIM];
    __shared__ float red[256];
    int b = blockIdx.x, tid = threadIdx.x;
    sx[tid] = X[b * DIM + tid];
    __syncthreads();
    int j = tid & 63, q = tid >> 6;
    const float* xj = X + (size_t)j * DIM + q * 64;
    const float* xb = sx + q * 64;
    float p = 0.f;
#pragma unroll
    for (int k = 0; k < 64; ++k) p += xb[k] * xj[k];
    red[tid] = p;
    __syncthreads();
    if (tid < 64)
        g_G[b * NS + tid] = red[tid] + red[tid + 64] + red[tid + 128] + red[tid + 192];
}

// ---------------- K2: D = X V^T (+ DT) and vnorms; 8x8 FFMA2 tile, 2 CTA/SM ----------------
__global__ __launch_bounds__(256, 2) void k_gemm(const float* __restrict__ X, const float* __restrict__ V) {
    __shared__ __align__(16) float sX[32][68];    // [k][s]
    __shared__ __align__(16) float sV[32][260];   // [k][j]
    int tid = threadIdx.x;
    int j0 = blockIdx.x * NPC;
    int nvalid = N_NODES - j0; if (nvalid > NPC) nvalid = NPC;

    int sg = tid & 7, ng = tid >> 3;      // compute mapping: 8 sample-groups x 32 node-groups
    int xs = tid & 63, xf = tid >> 6;     // X loader
    bool vok = tid < nvalid;
    const float* Vrow = V + (size_t)(vok ? (j0 + tid) : 0) * DIM;
    const float* Xrow = X + (size_t)xs * DIM;

    u64 acc[8][4];
#pragma unroll
    for (int a = 0; a < 8; ++a)
#pragma unroll
        for (int p = 0; p < 4; ++p) acc[a][p] = 0ull;
    float vnacc = 0.f;

    float4 rfv[8];
#pragma unroll
    for (int u = 0; u < 8; ++u)
        rfv[u] = vok ? *(const float4*)(Vrow + u * 4) : make_float4(0.f, 0.f, 0.f, 0.f);

    for (int kc = 0; kc < DIM; kc += 32) {
        // X tile direct global->smem (64KB total; L2-resident after first wave)
#pragma unroll
        for (int u = 0; u < 2; ++u) {
            int kof = xf * 8 + u * 4;
            float4 f = __ldg((const float4*)(Xrow + kc + kof));
            sX[kof + 0][xs] = f.x; sX[kof + 1][xs] = f.y;
            sX[kof + 2][xs] = f.z; sX[kof + 3][xs] = f.w;
        }
        // V tile from prefetched registers
#pragma unroll
        for (int u = 0; u < 8; ++u) {
            int kof = u * 4;
            sV[kof + 0][tid] = rfv[u].x; sV[kof + 1][tid] = rfv[u].y;
            sV[kof + 2][tid] = rfv[u].z; sV[kof + 3][tid] = rfv[u].w;
            vnacc += rfv[u].x * rfv[u].x + rfv[u].y * rfv[u].y
                   + rfv[u].z * rfv[u].z + rfv[u].w * rfv[u].w;
        }
        __syncthreads();
        if (kc + 32 < DIM) {   // prefetch next V chunk into registers (overlaps compute)
#pragma unroll
            for (int u = 0; u < 8; ++u)
                rfv[u] = vok ? *(const float4*)(Vrow + kc + 32 + u * 4)
                             : make_float4(0.f, 0.f, 0.f, 0.f);
        }
#pragma unroll
        for (int kk = 0; kk < 32; ++kk) {
            float4 xa = *(const float4*)&sX[kk][sg * 8];
            float4 xb = *(const float4*)&sX[kk][sg * 8 + 4];
            ulonglong2 va = *(const ulonglong2*)&sV[kk][ng * 8];
            ulonglong2 vb = *(const ulonglong2*)&sV[kk][ng * 8 + 4];
            u64 xp[8];
            xp[0] = fpack(xa.x); xp[1] = fpack(xa.y); xp[2] = fpack(xa.z); xp[3] = fpack(xa.w);
            xp[4] = fpack(xb.x); xp[5] = fpack(xb.y); xp[6] = fpack(xb.z); xp[7] = fpack(xb.w);
#pragma unroll
            for (int a = 0; a < 8; ++a) {
                acc[a][0] = f2fma(xp[a], va.x, acc[a][0]);
                acc[a][1] = f2fma(xp[a], va.y, acc[a][1]);
                acc[a][2] = f2fma(xp[a], vb.x, acc[a][2]);
                acc[a][3] = f2fma(xp[a], vb.y, acc[a][3]);
            }
        }
        __syncthreads();
    }

    if (vok) g_vn[j0 + tid] = vnacc;

    float accf[8][8];
#pragma unroll
    for (int a = 0; a < 8; ++a)
#pragma unroll
        for (int p = 0; p < 4; ++p) funpack(acc[a][p], accf[a][2 * p], accf[a][2 * p + 1]);

    int jb = ng * 8;
    if (jb < nvalid) {
        bool full = (jb + 8 <= nvalid);
#pragma unroll
        for (int a = 0; a < 8; ++a) {
            int s = sg * 8 + a;
            float* dst = g_D + (size_t)s * N_NODES + j0 + jb;
            if (full) {
                *(float4*)dst       = make_float4(accf[a][0], accf[a][1], accf[a][2], accf[a][3]);
                *(float4*)(dst + 4) = make_float4(accf[a][4], accf[a][5], accf[a][6], accf[a][7]);
            } else {
                for (int c = 0; c < 8; ++c) if (jb + c < nvalid) dst[c] = accf[a][c];
            }
        }
#pragma unroll
        for (int c = 0; c < 8; ++c) {
            if (full || jb + c < nvalid) {
                float* dst = &g_DT[(size_t)(j0 + jb + c) * NS + sg * 8];
                *(float4*)dst       = make_float4(accf[0][c], accf[1][c], accf[2][c], accf[3][c]);
                *(float4*)(dst + 4) = make_float4(accf[4][c], accf[5][c], accf[6][c], accf[7][c]);
            }
        }
    }
}

// ---------------- K3: per (sample,slice) top-CANDN via PQ + top-k selection network ----------------
__global__ __launch_bounds__(256) void k_cand() {
    __shared__ u64 keys[2048];
    int slice = blockIdx.x, i = blockIdx.y, tid = threadIdx.x;
    float xn = __ldg(&g_G[i * NS + i]);
    const float* Drow = g_D + (size_t)i * N_NODES;
    int base = slice * SLICEN, jend = base + SLICEN;

    u64 K[TK];
#pragma unroll
    for (int m = 0; m < TK; ++m) K[m] = ~0ull;

    for (int j = base + tid; j < jend; j += 1024) {
        float d[4]; int jj[4]; bool ok[4];
#pragma unroll
        for (int q = 0; q < 4; ++q) {
            jj[q] = j + q * 256;
            ok[q] = jj[q] < jend;
            int js = ok[q] ? jj[q] : base;
            d[q] = xn - 2.f * __ldg(&Drow[js]) + __ldg(&g_vn[js]);
        }
#pragma unroll
        for (int q = 0; q < 4; ++q) {
            if (ok[q]) {
                u64 key = ((u64)__float_as_uint(d[q]) << 32) | (unsigned)jj[q];
                if (key < K[TK - 1]) {
                    K[TK - 1] = key;
#pragma unroll
                    for (int m = TK - 1; m > 0; --m) {
                        u64 a = u64min(K[m - 1], K[m]);
                        u64 b = u64max(K[m - 1], K[m]);
                        K[m - 1] = a; K[m] = b;
                    }
                }
            }
        }
    }
    // store per-thread run; odd threads reversed so 16-blocks are bitonic
#pragma unroll
    for (int m = 0; m < TK; ++m)
        keys[tid * TK + m] = (tid & 1) ? K[TK - 1 - m] : K[m];
    __syncthreads();

    // bitonic continue from k=16 up to 256 (final level forced ascending per 256-block)
    for (int k = 16; k <= 256; k <<= 1) {
        for (int j2 = k >> 1; j2 > 0; j2 >>= 1) {
            for (int t = tid; t < 1024; t += 256) {
                int a = ((t & ~(j2 - 1)) << 1) | (t & (j2 - 1));
                bool up = (k == 256) ? true : ((a & k) == 0);
                u64 x = keys[a], y = keys[a + j2];
                if ((x > y) == up) { keys[a] = y; keys[a + j2] = x; }
            }
            __syncthreads();
        }
    }
    // top-k merge: 8 sorted 256-blocks -> 256 via halver + clean, 3 levels
#pragma unroll
    for (int L = 0; L < 3; ++L) {
        int npairs = 4 >> L;
        int pairstride = 512 << L;
        int nops = npairs << 8;
        for (int t = tid; t < nops; t += 256) {
            int p = t >> 8, ii = t & 255;
            int a = p * pairstride + ii;
            int b = p * pairstride + (pairstride >> 1) + 255 - ii;
            u64 x = keys[a], y = keys[b];
            if (y < x) { keys[a] = y; keys[b] = x; }
        }
        __syncthreads();
        for (int j2 = 128; j2 > 0; j2 >>= 1) {
            int cops = npairs << 7;
            for (int t = tid; t < cops; t += 256) {
                int p = t >> 7, q = t & 127;
                int idx = ((q & ~(j2 - 1)) << 1) | (q & (j2 - 1));
                int a = p * pairstride + idx;
                u64 x = keys[a], y = keys[a + j2];
                if (y < x) { keys[a] = y; keys[a + j2] = x; }
            }
            __syncthreads();
        }
    }
    if (tid < CANDN)
        g_scand[((size_t)i * NSLICE + slice) * CANDN + tid] = keys[tid];
}

// ---------------- K3b: merge 8 sorted lists -> global top-160 ----------------
__global__ __launch_bounds__(512) void k_merge() {
    __shared__ u64 keys[2048];
    int i = blockIdx.x, tid = threadIdx.x;
    for (int t = tid; t < 2048; t += 512) {
        int list = t >> 8, pos = t & 255;
        keys[t] = (pos < CANDN) ? __ldg(&g_scand[((size_t)i * NSLICE + list) * CANDN + pos]) : ~0ull;
    }
    __syncthreads();
#pragma unroll
    for (int L = 0; L < 3; ++L) {
        int npairs = 4 >> L;
        int pairstride = 512 << L;
        int nops = npairs << 8;
        for (int t = tid; t < nops; t += 512) {
            int p = t >> 8, ii = t & 255;
            int a = p * pairstride + ii;
            int b = p * pairstride + (pairstride >> 1) + 255 - ii;
            u64 x = keys[a], y = keys[b];
            if (y < x) { keys[a] = y; keys[b] = x; }
        }
        __syncthreads();
        for (int j2 = 128; j2 > 0; j2 >>= 1) {
            int cops = npairs << 7;
            for (int t = tid; t < cops; t += 512) {
                int p = t >> 7, q = t & 127;
                int idx = ((q & ~(j2 - 1)) << 1) | (q & (j2 - 1));
                int a = p * pairstride + idx;
                u64 x = keys[a], y = keys[a + j2];
                if (y < x) { keys[a] = y; keys[a + j2] = x; }
            }
            __syncthreads();
        }
    }
    if (tid < CANDN) g_cand[i * CANDN + tid] = keys[tid];
}

// ---------------- K4: sequential BMU loop, single warp, flat masked selection ----------------
#define SEQ_SMEM (NS * CANDN * 8 + NS * NS * 4 + 64 * 129 * 4 + MODCAP * 4 + MODCAP * 4 + HSHN * 4 + BMW * 4 + 64)

__global__ __launch_bounds__(256) void k_seq(const int* __restrict__ itp, float* __restrict__ out) {
    extern __shared__ char smraw[];
    u64*      scand = (u64*)smraw;                  // NS*CANDN
    float*    sG    = (float*)(scand + NS * CANDN); // NS*NS
    float*    mdt   = sG + NS * NS;                 // 64*129 : mdt[t][m]
    float*    mvn   = mdt + 64 * 129;               // MODCAP
    int*      midx  = (int*)(mvn + MODCAP);         // MODCAP
    int*      hsh   = midx + MODCAP;                // HSHN
    unsigned* bm    = (unsigned*)(hsh + HSHN);      // BMW

    int tid = threadIdx.x;
    for (int t = tid; t < NS * CANDN; t += 256) scand[t] = __ldg(&g_cand[t]);
    for (int t = tid; t < NS * NS; t += 256) sG[t] = __ldg(&g_G[t]);
    for (int t = tid; t < BMW; t += 256) bm[t] = 0;
    for (int t = tid; t < HSHN; t += 256) hsh[t] = 0;
    __syncthreads();
    if (tid >= 32) return;   // single warp

    int lane = tid;
    int it = itp ? __ldg(itp) : 0;
    float eb = 1.0f / (float)(it + 2);
    float en = 1.0f / (float)((it + 1) * 100);
    float ebo = 1.f - eb, eno = 1.f - en;

    // prefetch top-4 candidate DT rows + vnorms for sample 0
    unsigned pi0, pi1, pi2, pi3;
    float pf0a, pf1a, pf2a, pf3a, pf0b, pf1b, pf2b, pf3b, pfvn = 0.f;
    pi0 = (unsigned)scand[0]; pi1 = (unsigned)scand[1];
    pi2 = (unsigned)scand[2]; pi3 = (unsigned)scand[3];
    pf0a = __ldg(&g_DT[(size_t)pi0 * NS + lane]); pf0b = __ldg(&g_DT[(size_t)pi0 * NS + 32 + lane]);
    pf1a = __ldg(&g_DT[(size_t)pi1 * NS + lane]); pf1b = __ldg(&g_DT[(size_t)pi1 * NS + 32 + lane]);
    pf2a = __ldg(&g_DT[(size_t)pi2 * NS + lane]); pf2b = __ldg(&g_DT[(size_t)pi2 * NS + 32 + lane]);
    pf3a = __ldg(&g_DT[(size_t)pi3 * NS + lane]); pf3b = __ldg(&g_DT[(size_t)pi3 * NS + 32 + lane]);
    if (lane < 4) pfvn = __ldg(&g_vn[(unsigned)scand[lane]]);
    int nmod = 0;

    for (int i = 0; i < NS; ++i) {
        float xn = sG[i * NS + i];

        // ---- flat masked selection: unmodified candidates + mod table ----
        u64 k1 = ~0ull, k2 = ~0ull;
#pragma unroll
        for (int q = 0; q < 5; ++q) {
            u64 key = scand[i * CANDN + q * 32 + lane];
            unsigned idx = (unsigned)key;
            if (!((bm[idx >> 5] >> (idx & 31)) & 1u)) {
                if (key < k1) { k2 = k1; k1 = key; } else if (key < k2) k2 = key;
            }
        }
        int qmax = (nmod + 31) >> 5;
        for (int q = 0; q < qmax; ++q) {
            int m = q * 32 + lane;
            if (m < nmod) {
                float d2 = xn - 2.f * mdt[i * 129 + m] + mvn[m];
                u64 key = ((u64)__float_as_uint(d2) << 32) | (unsigned)midx[m];
                if (key < k1) { k2 = k1; k1 = key; } else if (key < k2) k2 = key;
            }
        }
#pragma unroll
        for (int off = 16; off; off >>= 1) {
            u64 b1 = __shfl_xor_sync(0xffffffffu, k1, off);
            u64 b2 = __shfl_xor_sync(0xffffffffu, k2, off);
            u64 m1 = u64min(k1, b1);
            u64 m2 = u64min(u64max(k1, b1), u64min(k2, b2));
            k1 = m1; k2 = m2;
        }
        unsigned nb = (unsigned)k1, nsd = (unsigned)k2;
        bool newb = !((bm[nb >> 5] >> (nb & 31)) & 1u);
        bool news = !((bm[nsd >> 5] >> (nsd & 31)) & 1u);

        if (lane == 2) {
            out[2 * i]     = sqrtf(__uint_as_float((unsigned)(k1 >> 32)) + 1e-12f);
            out[2 * i + 1] = sqrtf(__uint_as_float((unsigned)(k2 >> 32)) + 1e-12f);
        }

        // ---- slot resolution: concurrent probes on lanes 0/1 ----
        int sb = 0, ss = 0;
        if (lane == 0 && !newb) {
            unsigned h = (nb * 2654435761u) >> 21;
            while (true) {
                int e = hsh[h];
                if (e && midx[e - 1] == (int)nb) { sb = e - 1; break; }
                h = (h + 1) & (HSHN - 1);
            }
        }
        if (lane == 1 && !news) {
            unsigned h = (nsd * 2654435761u) >> 21;
            while (true) {
                int e = hsh[h];
                if (e && midx[e - 1] == (int)nsd) { ss = e - 1; break; }
                h = (h + 1) & (HSHN - 1);
            }
        }
        int sbh = __shfl_sync(0xffffffffu, sb, 0);
        int ssh = __shfl_sync(0xffffffffu, ss, 1);
        int slot_b = newb ? nmod : sbh;
        int slot_s = news ? (nmod + (newb ? 1 : 0)) : ssh;

        // ---- gather old rows ----
        float ob0, ob1, os0, os1, vnb, vns;
        if (newb) {
            int sel = (nb == pi0) ? 0 : (nb == pi1) ? 1 : (nb == pi2) ? 2 : (nb == pi3) ? 3 : -1;
            if (sel >= 0) {
                ob0 = sel == 0 ? pf0a : sel == 1 ? pf1a : sel == 2 ? pf2a : pf3a;
                ob1 = sel == 0 ? pf0b : sel == 1 ? pf1b : sel == 2 ? pf2b : pf3b;
                vnb = __shfl_sync(0xffffffffu, pfvn, sel);
            } else {
                ob0 = __ldg(&g_DT[(size_t)nb * NS + lane]);
                ob1 = __ldg(&g_DT[(size_t)nb * NS + 32 + lane]);
                vnb = __ldg(&g_vn[nb]);
            }
        } else {
            ob0 = mdt[lane * 129 + slot_b];
            ob1 = mdt[(32 + lane) * 129 + slot_b];
            vnb = mvn[slot_b];
        }
        if (news) {
            int sel = (nsd == pi0) ? 0 : (nsd == pi1) ? 1 : (nsd == pi2) ? 2 : (nsd == pi3) ? 3 : -1;
            if (sel >= 0) {
                os0 = sel == 0 ? pf0a : sel == 1 ? pf1a : sel == 2 ? pf2a : pf3a;
                os1 = sel == 0 ? pf0b : sel == 1 ? pf1b : sel == 2 ? pf2b : pf3b;
                vns = __shfl_sync(0xffffffffu, pfvn, sel);
            } else {
                os0 = __ldg(&g_DT[(size_t)nsd * NS + lane]);
                os1 = __ldg(&g_DT[(size_t)nsd * NS + 32 + lane]);
                vns = __ldg(&g_vn[nsd]);
            }
        } else {
            os0 = mdt[lane * 129 + slot_s];
            os1 = mdt[(32 + lane) * 129 + slot_s];
            vns = mvn[slot_s];
        }
        float obi = __shfl_sync(0xffffffffu, (i < 32) ? ob0 : ob1, i & 31);
        float osi = __shfl_sync(0xffffffffu, (i < 32) ? os0 : os1, i & 31);

        __syncwarp();   // reads of mdt/mvn/bm/hsh complete before mutation

        float gr0 = sG[i * NS + lane], gr1 = sG[i * NS + 32 + lane];
        mdt[lane * 129 + slot_b]        = ebo * ob0 + eb * gr0;
        mdt[(32 + lane) * 129 + slot_b] = ebo * ob1 + eb * gr1;
        mdt[lane * 129 + slot_s]        = eno * os0 + en * gr0;
        mdt[(32 + lane) * 129 + slot_s] = eno * os1 + en * gr1;
        if (lane == 0) {
            mvn[slot_b] = ebo * ebo * vnb + 2.f * eb * ebo * obi + eb * eb * xn;
            if (newb) {
                midx[slot_b] = (int)nb;
                atomicOr(&bm[nb >> 5], 1u << (nb & 31));
                unsigned h = (nb * 2654435761u) >> 21;
                while (atomicCAS(&hsh[h], 0, slot_b + 1) != 0) h = (h + 1) & (HSHN - 1);
            }
        }
        if (lane == 1) {
            mvn[slot_s] = eno * eno * vns + 2.f * en * eno * osi + en * en * xn;
            if (news) {
                midx[slot_s] = (int)nsd;
                atomicOr(&bm[nsd >> 5], 1u << (nsd & 31));
                unsigned h = (nsd * 2654435761u) >> 21;
                while (atomicCAS(&hsh[h], 0, slot_s + 1) != 0) h = (h + 1) & (HSHN - 1);
            }
        }
        nmod += (newb ? 1 : 0) + (news ? 1 : 0);

        // prefetch next sample's top-4 candidate rows + vnorms (off critical path)
        if (i + 1 < NS) {
            pi0 = (unsigned)scand[(i + 1) * CANDN + 0];
            pi1 = (unsigned)scand[(i + 1) * CANDN + 1];
            pi2 = (unsigned)scand[(i + 1) * CANDN + 2];
            pi3 = (unsigned)scand[(i + 1) * CANDN + 3];
            pf0a = __ldg(&g_DT[(size_t)pi0 * NS + lane]); pf0b = __ldg(&g_DT[(size_t)pi0 * NS + 32 + lane]);
            pf1a = __ldg(&g_DT[(size_t)pi1 * NS + lane]); pf1b = __ldg(&g_DT[(size_t)pi1 * NS + 32 + lane]);
            pf2a = __ldg(&g_DT[(size_t)pi2 * NS + lane]); pf2b = __ldg(&g_DT[(size_t)pi2 * NS + 32 + lane]);
            pf3a = __ldg(&g_DT[(size_t)pi3 * NS + lane]); pf3b = __ldg(&g_DT[(size_t)pi3 * NS + 32 + lane]);
            if (lane < 4) pfvn = __ldg(&g_vn[(unsigned)scand[(i + 1) * CANDN + lane]]);
        }
        __syncwarp();   // mutations visible before next selection
    }
}

extern "C" void kernel_launch(void* const* d_in, const int* in_sizes, int n_in,
                              void* d_out, int out_size) {
    const float* X = (const float*)d_in[0];     // data [64,256]
    const float* V = (const float*)d_in[1];     // V [100000,256]
    const int* itp = (n_in > 3) ? (const int*)d_in[3] : nullptr;
    float* out = (float*)d_out;                 // [64,2]

    cudaFuncSetAttribute(k_seq, cudaFuncAttributeMaxDynamicSharedMemorySize, SEQ_SMEM);

    // one shim launch so ncu's fixed 4th-launch capture slot lands on k_cand
    k_nop<<<1, 32>>>();

    k_gram<<<NS, 256>>>(X);
    k_gemm<<<(N_NODES + NPC - 1) / NPC, 256>>>(X, V);
    k_cand<<<dim3(NSLICE, NS), 256>>>();
    k_merge<<<NS, 512>>>();
    k_seq<<<1, 256, SEQ_SMEM>>>(itp, out);
}